// round 1
// baseline (speedup 1.0000x reference)
#include <cuda_runtime.h>
#include <math.h>

// Problem constants
#define DEPTH 16
#define NN    65535          // 2^16 - 1 nodes, heap order
#define H     256
#define DIN   256
#define KIN   768            // DIN + 2*H
#define NC    1280           // 5 gate groups * H  (i, o, u, f0, f1)

// Tiling
#define BM 16                // nodes per block tile
#define BJ 64                // hidden units per block tile (=> 5*BJ = 320 gemm cols)
#define KT 32                // k tile

// Scratch (device globals; no cudaMalloc allowed)
__device__ float g_h[(size_t)NN * H];        // 67 MB
__device__ float g_c[(size_t)NN * H];        // 67 MB
__device__ float g_W[(size_t)KIN * NC];      // 3.93 MB, layout [k][j*5+g]
__device__ float g_b[NC];                    // packed bias [j*5+g]

// ---------------------------------------------------------------------------
// Pack combined weight matrix + bias.
// Columns: col = j*5 + g,  g in {0:i, 1:o, 2:u, 3:f0, 4:f1}
// Rows:    k <256: x part (W_g[j][k]; f0,f1 both use W_f)
//          256..511: child0 h (U_g[0][j][k-256]; f1 gets 0)
//          512..767: child1 h (U_g[1][j][k-512]; f0 gets 0)
// ---------------------------------------------------------------------------
__global__ void pack_kernel(
    const float* __restrict__ Wi, const float* __restrict__ bi, const float* __restrict__ Ui,
    const float* __restrict__ Wo, const float* __restrict__ bo, const float* __restrict__ Uo,
    const float* __restrict__ Wu, const float* __restrict__ bu, const float* __restrict__ Uu,
    const float* __restrict__ Wf, const float* __restrict__ bf, const float* __restrict__ Uf)
{
    int idx = blockIdx.x * blockDim.x + threadIdx.x;
    if (idx < NC) {
        int j = idx / 5, g = idx % 5;
        float b = (g == 0) ? bi[j] : (g == 1) ? bo[j] : (g == 2) ? bu[j] : bf[j];
        g_b[idx] = b;
    }
    int stride = gridDim.x * blockDim.x;
    for (int e = idx; e < KIN * NC; e += stride) {
        int k   = e / NC;
        int col = e % NC;
        int j = col / 5, g = col % 5;
        float v = 0.f;
        if (k < DIN) {
            const float* W = (g == 0) ? Wi : (g == 1) ? Wo : (g == 2) ? Wu : Wf;
            v = W[j * DIN + k];
        } else if (k < DIN + H) {
            int kk = k - DIN;
            if      (g == 0) v = Ui[j * H + kk];
            else if (g == 1) v = Uo[j * H + kk];
            else if (g == 2) v = Uu[j * H + kk];
            else if (g == 3) v = Uf[j * H + kk];
            // g == 4 -> 0
        } else {
            int kk = k - DIN - H;
            if      (g == 0) v = Ui[H * H + j * H + kk];
            else if (g == 1) v = Uo[H * H + j * H + kk];
            else if (g == 2) v = Uu[H * H + j * H + kk];
            else if (g == 4) v = Uf[H * H + j * H + kk];
            // g == 3 -> 0
        }
        g_W[e] = v;
    }
}

__device__ __forceinline__ float sigmoidf_(float x) {
    return 1.f / (1.f + expf(-x));
}

// ---------------------------------------------------------------------------
// One tree level: fused GEMM [n x K] @ [K x 1280] + gate epilogue.
// Block: 256 threads. tx = t & 63 (hidden unit in tile), ty = t >> 6.
// Thread computes nodes m = ty + 4*i (i in 0..3), all 5 gates of unit j0+tx.
// ---------------------------------------------------------------------------
template <bool HASCH>
__global__ void __launch_bounds__(256) level_kernel(
    const float* __restrict__ emb, int start, int n,
    float* __restrict__ out, int out_size)
{
    __shared__ float As[KT][17];        // [kk][m], padded: conflict-free stores
    __shared__ float Ws[KT][5 * BJ];    // [kk][320]

    const int t  = threadIdx.x;
    const int tx = t & 63;
    const int ty = t >> 6;
    const int j0 = blockIdx.x * BJ;
    const int m0 = blockIdx.y * BM;

    float acc[4][5];
#pragma unroll
    for (int i = 0; i < 4; ++i)
#pragma unroll
        for (int g = 0; g < 5; ++g) acc[i][g] = 0.f;

    const int KTOT = HASCH ? KIN : DIN;

    for (int k0 = 0; k0 < KTOT; k0 += KT) {
        // --- load A tile (gathered: emb | h(child0) | h(child1)) ---
        {
            int kk = t & 31;       // coalesced along k
            int m  = t >> 5;       // 0..7, then +8
#pragma unroll
            for (int r = 0; r < 2; ++r, m += 8) {
                int node = m0 + m;
                float v = 0.f;
                if (node < n) {
                    int gn = start + node;
                    int k  = k0 + kk;
                    if (k < DIN)            v = emb[(size_t)gn * DIN + k];
                    else if (HASCH) {
                        if (k < DIN + H)    v = g_h[(size_t)(2 * gn + 1) * H + (k - DIN)];
                        else                v = g_h[(size_t)(2 * gn + 2) * H + (k - DIN - H)];
                    }
                }
                As[kk][m] = v;
            }
        }
        // --- load W tile: 32 rows x 320 cols, vectorized float4 ---
        {
#pragma unroll
            for (int r = 0; r < 10; ++r) {
                int e   = t + r * 256;       // 0..2559 float4 slots
                int row = e / 80;            // 80 float4 per row
                int lc  = e - row * 80;
                const float4* src = reinterpret_cast<const float4*>(
                    &g_W[(size_t)(k0 + row) * NC + j0 * 5]);
                *reinterpret_cast<float4*>(&Ws[row][lc * 4]) = src[lc];
            }
        }
        __syncthreads();

#pragma unroll
        for (int kk = 0; kk < KT; ++kk) {
            float a0 = As[kk][ty];
            float a1 = As[kk][ty + 4];
            float a2 = As[kk][ty + 8];
            float a3 = As[kk][ty + 12];
            float w0 = Ws[kk][tx * 5 + 0];
            float w1 = Ws[kk][tx * 5 + 1];
            float w2 = Ws[kk][tx * 5 + 2];
            float w3 = Ws[kk][tx * 5 + 3];
            float w4 = Ws[kk][tx * 5 + 4];
            acc[0][0] += a0 * w0; acc[0][1] += a0 * w1; acc[0][2] += a0 * w2;
            acc[0][3] += a0 * w3; acc[0][4] += a0 * w4;
            acc[1][0] += a1 * w0; acc[1][1] += a1 * w1; acc[1][2] += a1 * w2;
            acc[1][3] += a1 * w3; acc[1][4] += a1 * w4;
            acc[2][0] += a2 * w0; acc[2][1] += a2 * w1; acc[2][2] += a2 * w2;
            acc[2][3] += a2 * w3; acc[2][4] += a2 * w4;
            acc[3][0] += a3 * w0; acc[3][1] += a3 * w1; acc[3][2] += a3 * w2;
            acc[3][3] += a3 * w3; acc[3][4] += a3 * w4;
        }
        __syncthreads();
    }

    // --- fused gate epilogue ---
    const int j  = j0 + tx;
    const float b0 = g_b[j * 5 + 0];
    const float b1 = g_b[j * 5 + 1];
    const float b2 = g_b[j * 5 + 2];
    const float b3 = g_b[j * 5 + 3];
    const float b4 = g_b[j * 5 + 4];

#pragma unroll
    for (int i = 0; i < 4; ++i) {
        int node = m0 + ty + 4 * i;
        if (node >= n) continue;
        int gn = start + node;
        float gi = sigmoidf_(acc[i][0] + b0);
        float go = sigmoidf_(acc[i][1] + b1);
        float gu = tanhf(acc[i][2] + b2);
        float c  = gi * gu;
        if (HASCH) {
            float f0 = sigmoidf_(acc[i][3] + b3);
            float f1 = sigmoidf_(acc[i][4] + b4);
            c += f0 * g_c[(size_t)(2 * gn + 1) * H + j]
               + f1 * g_c[(size_t)(2 * gn + 2) * H + j];
        }
        float h = go * tanhf(c);
        g_h[(size_t)gn * H + j] = h;
        g_c[(size_t)gn * H + j] = c;
        if (out != nullptr && gn == 0) {
            out[j] = h;
            if (out_size >= 2 * H) out[H + j] = c;
        }
    }
}

// ---------------------------------------------------------------------------
extern "C" void kernel_launch(void* const* d_in, const int* in_sizes, int n_in,
                              void* d_out, int out_size)
{
    const float* emb = (const float*)d_in[0];
    const float* Wi  = (const float*)d_in[1];
    const float* bi  = (const float*)d_in[2];
    const float* Ui  = (const float*)d_in[3];
    const float* Wo  = (const float*)d_in[4];
    const float* bo  = (const float*)d_in[5];
    const float* Uo  = (const float*)d_in[6];
    const float* Wu  = (const float*)d_in[7];
    const float* bu  = (const float*)d_in[8];
    const float* Uu  = (const float*)d_in[9];
    const float* Wf  = (const float*)d_in[10];
    const float* bf  = (const float*)d_in[11];
    const float* Uf  = (const float*)d_in[12];

    pack_kernel<<<512, 256>>>(Wi, bi, Ui, Wo, bo, Uo, Wu, bu, Uu, Wf, bf, Uf);

    // leaves: level DEPTH-1, no children
    {
        int n = 1 << (DEPTH - 1);
        int start = n - 1;
        dim3 grid(H / BJ, (n + BM - 1) / BM);
        level_kernel<false><<<grid, 256>>>(emb, start, n, nullptr, out_size);
    }
    // internal levels bottom-up
    for (int l = DEPTH - 2; l >= 0; --l) {
        int n = 1 << l;
        int start = n - 1;
        dim3 grid(H / BJ, (n + BM - 1) / BM);
        float* outp = (l == 0) ? (float*)d_out : nullptr;
        level_kernel<true><<<grid, 256>>>(emb, start, n, outp, out_size);
    }
}

// round 2
// speedup vs baseline: 1.2818x; 1.2818x over previous
#include <cuda_runtime.h>
#include <math.h>

// Problem constants
#define DEPTH 16
#define NN    65535          // 2^16 - 1 nodes, heap order
#define H     256
#define DIN   256
#define KIN   768            // DIN + 2*H
#define KT    32             // k tile

// Scratch (device globals; no cudaMalloc allowed)
__device__ float g_h[(size_t)NN * H];          // 67 MB
__device__ float g_c[(size_t)NN * H];          // 67 MB
__device__ float g_W[(size_t)5 * KIN * H];     // 3.93 MB, layout [g][k][j]
__device__ float g_b[5 * H];                   // bias [g][j]

// ---------------------------------------------------------------------------
// Pack weights: g_W[(g*KIN + k)*H + j]
//   g: 0=i 1=o 2=u 3=f(child0) 4=f(child1)
//   k <256:      x part    -> W_g[j][k]      (g3,g4 both W_f)
//   256..511:    child0 h  -> U_g[0][j][kk]  (g4 -> 0)
//   512..767:    child1 h  -> U_g[1][j][kk]  (g3 -> 0)
// Bias: g_b[g*H + j]
// ---------------------------------------------------------------------------
__global__ void pack_kernel(
    const float* __restrict__ Wi, const float* __restrict__ bi, const float* __restrict__ Ui,
    const float* __restrict__ Wo, const float* __restrict__ bo, const float* __restrict__ Uo,
    const float* __restrict__ Wu, const float* __restrict__ bu, const float* __restrict__ Uu,
    const float* __restrict__ Wf, const float* __restrict__ bf, const float* __restrict__ Uf)
{
    int idx = blockIdx.x * blockDim.x + threadIdx.x;
    if (idx < 5 * H) {
        int g = idx / H, j = idx % H;
        g_b[idx] = (g == 0) ? bi[j] : (g == 1) ? bo[j] : (g == 2) ? bu[j] : bf[j];
    }
    int stride = gridDim.x * blockDim.x;
    for (int e = idx; e < 5 * KIN * H; e += stride) {
        int g = e / (KIN * H);
        int r = e - g * (KIN * H);
        int k = r / H;
        int j = r - k * H;
        float v = 0.f;
        if (k < DIN) {
            const float* W = (g == 0) ? Wi : (g == 1) ? Wo : (g == 2) ? Wu : Wf;
            v = W[j * DIN + k];
        } else if (k < DIN + H) {
            int kk = k - DIN;
            if      (g == 0) v = Ui[j * H + kk];
            else if (g == 1) v = Uo[j * H + kk];
            else if (g == 2) v = Uu[j * H + kk];
            else if (g == 3) v = Uf[j * H + kk];
        } else {
            int kk = k - DIN - H;
            if      (g == 0) v = Ui[H * H + j * H + kk];
            else if (g == 1) v = Uo[H * H + j * H + kk];
            else if (g == 2) v = Uu[H * H + j * H + kk];
            else if (g == 4) v = Uf[H * H + j * H + kk];
        }
        g_W[e] = v;
    }
}

__device__ __forceinline__ float sigmoidf_(float x) {
    return 1.f / (1.f + expf(-x));
}

// packed f32x2 helpers (sm_103a)
__device__ __forceinline__ void fma2(unsigned long long& d,
                                     unsigned long long a,
                                     unsigned long long b) {
    asm volatile("fma.rn.f32x2 %0, %1, %2, %0;" : "+l"(d) : "l"(a), "l"(b));
}
__device__ __forceinline__ unsigned long long splat2(float w) {
    unsigned long long r;
    asm("mov.b64 %0, {%1, %1};" : "=l"(r) : "f"(w));
    return r;
}
__device__ __forceinline__ void unpack2(unsigned long long v, float& lo, float& hi) {
    asm("mov.b64 {%0, %1}, %2;" : "=f"(lo), "=f"(hi) : "l"(v));
}

// ---------------------------------------------------------------------------
// One tree level, fused GEMM + gates, f32x2 packed math.
// Block: 256 threads. Tile: BM = 8*PAIRS nodes x 64 units (320 gemm cols).
// tx = t&63 -> hidden unit; ty = t>>6 (0..3) -> node-pair group.
// Thread computes PAIRS node-pairs x 5 gates, nodes packed 2/f32x2.
// ---------------------------------------------------------------------------
template <int PAIRS, bool HASCH>
__global__ void __launch_bounds__(256) level_kernel(
    const float* __restrict__ emb, int start, int n,
    float* __restrict__ out, int out_size)
{
    constexpr int BM = 8 * PAIRS;            // nodes per block
    constexpr int AST = PAIRS * 4 + 1;       // A row stride in float2 (padded)

    __shared__ float2 As2[KT][AST];          // [kk][node_pair]
    __shared__ float  Ws[5][KT][64];         // [gate][kk][unit]

    const int t  = threadIdx.x;
    const int tx = t & 63;
    const int ty = t >> 6;
    const int j0 = blockIdx.x * 64;
    const int m0 = blockIdx.y * BM;
    const int j  = j0 + tx;

    // bias -> init accumulators with (b,b)
    unsigned long long acc[PAIRS][5];
#pragma unroll
    for (int g = 0; g < 5; ++g) {
        unsigned long long b2 = splat2(g_b[g * H + j]);
#pragma unroll
        for (int p = 0; p < PAIRS; ++p) acc[p][g] = b2;
    }

    const int KTOT = HASCH ? KIN : DIN;

    for (int k0 = 0; k0 < KTOT; k0 += KT) {
        // --- A tile: BM nodes x KT k, gathered (emb | h(child0) | h(child1)) ---
        {
            int kk = t & 31;
            int mb = t >> 5;          // 0..7
            float* Af = reinterpret_cast<float*>(As2);
#pragma unroll
            for (int r = 0; r < BM / 8; ++r) {
                int m = mb + r * 8;
                int node = m0 + m;
                float v = 0.f;
                if (node < n) {
                    int gn = start + node;
                    int k  = k0 + kk;
                    if (k < DIN)          v = emb[(size_t)gn * DIN + k];
                    else if (HASCH) {
                        if (k < DIN + H)  v = g_h[(size_t)(2 * gn + 1) * H + (k - DIN)];
                        else              v = g_h[(size_t)(2 * gn + 2) * H + (k - DIN - H)];
                    }
                }
                Af[kk * (AST * 2) + m] = v;
            }
        }
        // --- W tile: 5 gate planes x KT rows x 64 units, float4 from [g][k][j] ---
        {
#pragma unroll
            for (int r = 0; r < 10; ++r) {
                int e   = t + r * 256;        // 0..2559 float4 slots
                int g   = e >> 9;             // 512 float4 per plane
                int rem = e & 511;
                int row = rem >> 4;           // 16 float4 per row
                int lc  = rem & 15;
                const float4* src = reinterpret_cast<const float4*>(
                    &g_W[(size_t)(g * KIN + k0 + row) * H + j0]);
                *reinterpret_cast<float4*>(&Ws[g][row][lc * 4]) = src[lc];
            }
        }
        __syncthreads();

#pragma unroll
        for (int kk = 0; kk < KT; ++kk) {
            const unsigned long long* arow =
                reinterpret_cast<const unsigned long long*>(&As2[kk][ty * PAIRS]);
            unsigned long long a2[PAIRS];
#pragma unroll
            for (int p = 0; p < PAIRS; ++p) a2[p] = arow[p];
            unsigned long long w2[5];
#pragma unroll
            for (int g = 0; g < 5; ++g) w2[g] = splat2(Ws[g][kk][tx]);
#pragma unroll
            for (int p = 0; p < PAIRS; ++p)
#pragma unroll
                for (int g = 0; g < 5; ++g)
                    fma2(acc[p][g], a2[p], w2[g]);
        }
        __syncthreads();
    }

    // --- gate epilogue, 2 nodes per pair ---
#pragma unroll
    for (int p = 0; p < PAIRS; ++p) {
        float gi[2], go[2], gu[2], f0[2], f1[2];
        unpack2(acc[p][0], gi[0], gi[1]);
        unpack2(acc[p][1], go[0], go[1]);
        unpack2(acc[p][2], gu[0], gu[1]);
        unpack2(acc[p][3], f0[0], f0[1]);
        unpack2(acc[p][4], f1[0], f1[1]);
#pragma unroll
        for (int s = 0; s < 2; ++s) {
            int node = m0 + (ty * PAIRS + p) * 2 + s;
            if (node >= n) continue;
            int gn = start + node;
            float vi = sigmoidf_(gi[s]);
            float vo = sigmoidf_(go[s]);
            float vu = tanhf(gu[s]);
            float c  = vi * vu;
            if (HASCH) {
                float vf0 = sigmoidf_(f0[s]);
                float vf1 = sigmoidf_(f1[s]);
                c += vf0 * g_c[(size_t)(2 * gn + 1) * H + j]
                   + vf1 * g_c[(size_t)(2 * gn + 2) * H + j];
            }
            float h = vo * tanhf(c);
            g_h[(size_t)gn * H + j] = h;
            g_c[(size_t)gn * H + j] = c;
            if (out != nullptr && gn == 0) {
                out[j] = h;
                if (out_size >= 2 * H) out[H + j] = c;
            }
        }
    }
}

// ---------------------------------------------------------------------------
extern "C" void kernel_launch(void* const* d_in, const int* in_sizes, int n_in,
                              void* d_out, int out_size)
{
    const float* emb = (const float*)d_in[0];
    const float* Wi  = (const float*)d_in[1];
    const float* bi  = (const float*)d_in[2];
    const float* Ui  = (const float*)d_in[3];
    const float* Wo  = (const float*)d_in[4];
    const float* bo  = (const float*)d_in[5];
    const float* Uo  = (const float*)d_in[6];
    const float* Wu  = (const float*)d_in[7];
    const float* bu  = (const float*)d_in[8];
    const float* Uu  = (const float*)d_in[9];
    const float* Wf  = (const float*)d_in[10];
    const float* bf  = (const float*)d_in[11];
    const float* Uf  = (const float*)d_in[12];

    pack_kernel<<<512, 256>>>(Wi, bi, Ui, Wo, bo, Uo, Wu, bu, Uu, Wf, bf, Uf);

    // leaves (n=32768), no children
    {
        int n = 1 << (DEPTH - 1);
        int start = n - 1;
        dim3 grid(4, (n + 31) / 32);
        level_kernel<4, false><<<grid, 256>>>(emb, start, n, nullptr, out_size);
    }
    // internal levels bottom-up
    for (int l = DEPTH - 2; l >= 0; --l) {
        int n = 1 << l;
        int start = n - 1;
        float* outp = (l == 0) ? (float*)d_out : nullptr;
        if (n >= 2048) {
            dim3 grid(4, (n + 31) / 32);
            level_kernel<4, true><<<grid, 256>>>(emb, start, n, outp, out_size);
        } else {
            dim3 grid(4, (n + 7) / 8);
            level_kernel<1, true><<<grid, 256>>>(emb, start, n, outp, out_size);
        }
    }
}

// round 4
// speedup vs baseline: 2.0595x; 1.6068x over previous
#include <cuda_runtime.h>
#include <cuda_bf16.h>
#include <cstdint>
#include <math.h>

#define DEPTH 16
#define NN    65535
#define H     256
#define KIN   768
#define NCOL  1280           // 5 gates * 256 units, col = j*5+g

// ---------------- device scratch (no cudaMalloc allowed) ----------------
__device__ __nv_bfloat16 g_ehi[(size_t)NN * H];
__device__ __nv_bfloat16 g_elo[(size_t)NN * H];
__device__ __nv_bfloat16 g_hhi[(size_t)NN * H];
__device__ __nv_bfloat16 g_hlo[(size_t)NN * H];
__device__ float         g_c  [(size_t)NN * H];
__device__ __nv_bfloat16 g_Bhi[(size_t)NCOL * KIN];   // [col][k]
__device__ __nv_bfloat16 g_Blo[(size_t)NCOL * KIN];
__device__ float         g_bias[NCOL];

// ---------------- smem layout ----------------
// A stage: 128 rows x 80B (32 bf16 + pad)  = 10240 B, x2 stages
// B stage:  80 rows x 80B                  =  6400 B, x2 stages
// C (epilogue, aliases A/B): 128 x 84 fp32 = 43008 B
static constexpr int OFF_AS   = 0;
static constexpr int OFF_BS   = 20480;
static constexpr int SMEM_DYN = 43520;

// ---------------- PTX helpers (baseline sm_80+, no 'a' features) ----------------
__device__ __forceinline__ uint32_t smem_to_u32(const void* p) {
    uint32_t a;
    asm("{ .reg .u64 t; cvta.to.shared.u64 t, %1; cvt.u32.u64 %0, t; }" : "=r"(a) : "l"(p));
    return a;
}
__device__ __forceinline__ void cpasync16(uint32_t dst, const void* src) {
    asm volatile("cp.async.cg.shared.global [%0], [%1], 16;" :: "r"(dst), "l"(src) : "memory");
}
#define CP_COMMIT() asm volatile("cp.async.commit_group;" ::: "memory")
#define CP_WAIT(N)  asm volatile("cp.async.wait_group %0;" :: "n"(N) : "memory")

__device__ __forceinline__ void ldsm4(uint32_t* r, uint32_t addr) {
    asm volatile("ldmatrix.sync.aligned.m8n8.x4.shared.b16 {%0,%1,%2,%3}, [%4];"
        : "=r"(r[0]), "=r"(r[1]), "=r"(r[2]), "=r"(r[3]) : "r"(addr));
}
__device__ __forceinline__ void ldsm2(uint32_t* r, uint32_t addr) {
    asm volatile("ldmatrix.sync.aligned.m8n8.x2.shared.b16 {%0,%1}, [%2];"
        : "=r"(r[0]), "=r"(r[1]) : "r"(addr));
}
__device__ __forceinline__ void mma16816(float* d, const uint32_t* a, const uint32_t* b) {
    asm volatile("mma.sync.aligned.m16n8k16.row.col.f32.bf16.bf16.f32 "
        "{%0,%1,%2,%3}, {%4,%5,%6,%7}, {%8,%9}, {%0,%1,%2,%3};"
        : "+f"(d[0]), "+f"(d[1]), "+f"(d[2]), "+f"(d[3])
        : "r"(a[0]), "r"(a[1]), "r"(a[2]), "r"(a[3]), "r"(b[0]), "r"(b[1]));
}

__device__ __forceinline__ float sigmoidf_(float x) { return 1.f / (1.f + expf(-x)); }

// ---------------- pack kernels ----------------
__global__ void split_emb_kernel(const float* __restrict__ emb) {
    int idx = blockIdx.x * blockDim.x + threadIdx.x;
    int stride = gridDim.x * blockDim.x;
    const int total4 = (NN * H) / 4;
    for (int i = idx; i < total4; i += stride) {
        float4 v = reinterpret_cast<const float4*>(emb)[i];
        __nv_bfloat16 hh[4], hl[4];
        float f[4] = {v.x, v.y, v.z, v.w};
#pragma unroll
        for (int k = 0; k < 4; ++k) {
            hh[k] = __float2bfloat16(f[k]);
            hl[k] = __float2bfloat16(f[k] - __bfloat162float(hh[k]));
        }
        reinterpret_cast<uint2*>(g_ehi)[i] = *reinterpret_cast<uint2*>(hh);
        reinterpret_cast<uint2*>(g_elo)[i] = *reinterpret_cast<uint2*>(hl);
    }
}

__global__ void pack_w_kernel(
    const float* __restrict__ Wi, const float* __restrict__ bi, const float* __restrict__ Ui,
    const float* __restrict__ Wo, const float* __restrict__ bo, const float* __restrict__ Uo,
    const float* __restrict__ Wu, const float* __restrict__ bu, const float* __restrict__ Uu,
    const float* __restrict__ Wf, const float* __restrict__ bf, const float* __restrict__ Uf)
{
    int idx = blockIdx.x * blockDim.x + threadIdx.x;
    int stride = gridDim.x * blockDim.x;
    if (idx < NCOL) {
        int j = idx / 5, g = idx % 5;
        g_bias[idx] = (g == 0) ? bi[j] : (g == 1) ? bo[j] : (g == 2) ? bu[j] : bf[j];
    }
    for (int e = idx; e < NCOL * KIN; e += stride) {
        int col = e / KIN;
        int k   = e - col * KIN;
        int j = col / 5, g = col % 5;
        float v = 0.f;
        if (k < H) {
            const float* W = (g == 0) ? Wi : (g == 1) ? Wo : (g == 2) ? Wu : Wf;
            v = W[j * H + k];
        } else if (k < 2 * H) {
            int kk = k - H;
            if      (g == 0) v = Ui[j * H + kk];
            else if (g == 1) v = Uo[j * H + kk];
            else if (g == 2) v = Uu[j * H + kk];
            else if (g == 3) v = Uf[j * H + kk];
        } else {
            int kk = k - 2 * H;
            if      (g == 0) v = Ui[H * H + j * H + kk];
            else if (g == 1) v = Uo[H * H + j * H + kk];
            else if (g == 2) v = Uu[H * H + j * H + kk];
            else if (g == 4) v = Uf[H * H + j * H + kk];
        }
        __nv_bfloat16 hi = __float2bfloat16(v);
        g_Bhi[e] = hi;
        g_Blo[e] = __float2bfloat16(v - __bfloat162float(hi));
    }
}

// ---------------- level kernel ----------------
// GEMM C[128 nodes][80 cols] += A'[128][K'] * B'[80][K']^T over K' = 3*KL,
// split s: s0 = Ahi*Bhi, s1 = Alo*Bhi, s2 = Ahi*Blo. Fused LSTM gate epilogue.
template <bool HASCH>
__global__ void __launch_bounds__(256, 2) hmma_level_kernel(
    int start, int n, float* __restrict__ out)
{
    extern __shared__ char smem[];
    const uint32_t sbase = smem_to_u32(smem);

    const int t    = threadIdx.x;
    const int lane = t & 31;
    const int wid  = t >> 5;
    const int cb   = blockIdx.x;          // 0..15 column blocks (80 cols each)
    const int m0   = blockIdx.y * 128;
    const int gn0  = start + m0;
    const int col0 = cb * 80;

    constexpr int KL  = HASCH ? KIN : H;  // 768 / 256
    constexpr int NCH = 3 * KL / 32;      // 72 / 24

    float acc[2][5][4];
#pragma unroll
    for (int mt = 0; mt < 2; ++mt)
#pragma unroll
        for (int nt = 0; nt < 5; ++nt)
#pragma unroll
            for (int r = 0; r < 4; ++r) acc[mt][nt][r] = 0.f;

    // ---- chunk loader: one 32-k slice of split s into stage st ----
    auto load_chunk = [&](int c, int st) {
        const int kk = c * 32;
        const int s  = kk / KL;
        const int k  = kk - s * KL;
        const __nv_bfloat16* abase;
        int astride;
        if (!HASCH || k < H) {
            abase = (s == 1 ? g_elo : g_ehi) + (size_t)gn0 * H + k;
            astride = H;
        } else if (k < 2 * H) {
            abase = (s == 1 ? g_hlo : g_hhi) + (size_t)(2 * gn0 + 1) * H + (k - H);
            astride = 2 * H;
        } else {
            abase = (s == 1 ? g_hlo : g_hhi) + (size_t)(2 * gn0 + 2) * H + (k - 2 * H);
            astride = 2 * H;
        }
        const __nv_bfloat16* bbase = (s == 2 ? g_Blo : g_Bhi) + (size_t)col0 * KIN + k;
        const uint32_t adst = sbase + OFF_AS + st * 10240;
        const uint32_t bdst = sbase + OFF_BS + st * 6400;
#pragma unroll
        for (int i = 0; i < 4; ++i) {
            int idx = t + i * 256;
            if (idx < 512) {
                int row = idx >> 2, seg = idx & 3;
                cpasync16(adst + row * 80 + seg * 16,
                          abase + (size_t)row * astride + seg * 8);
            } else if (idx < 832) {
                int r2 = idx - 512;
                int row = r2 >> 2, seg = r2 & 3;
                cpasync16(bdst + row * 80 + seg * 16,
                          bbase + (size_t)row * KIN + seg * 8);
            }
        }
        CP_COMMIT();
    };

    load_chunk(0, 0);

    const int wm = (wid & 3) * 32;
    const int wn = (wid >> 2) * 40;

    for (int c = 0; c < NCH; ++c) {
        const int st = c & 1;
        if (c + 1 < NCH) { load_chunk(c + 1, st ^ 1); CP_WAIT(1); }
        else             { CP_WAIT(0); }
        __syncthreads();

        const uint32_t abuf = sbase + OFF_AS + st * 10240;
        const uint32_t bbuf = sbase + OFF_BS + st * 6400;
#pragma unroll
        for (int k16 = 0; k16 < 2; ++k16) {
            uint32_t a[2][4], b[5][2];
            const int kb = k16 * 16;
            // A: two m16 tiles
#pragma unroll
            for (int mt = 0; mt < 2; ++mt) {
                uint32_t addr = abuf + (wm + mt * 16 + (lane & 15)) * 80
                              + (kb + ((lane >> 4) << 3)) * 2;
                ldsm4(a[mt], addr);
            }
            // B: tiles 0-3 via two x4, tile 4 via x2
#pragma unroll
            for (int p = 0; p < 2; ++p) {
                uint32_t r[4];
                uint32_t addr = bbuf
                    + (wn + p * 16 + ((lane >> 4) << 3) + (lane & 7)) * 80
                    + (kb + (((lane >> 3) & 1) << 3)) * 2;
                ldsm4(r, addr);
                b[p * 2 + 0][0] = r[0]; b[p * 2 + 0][1] = r[1];
                b[p * 2 + 1][0] = r[2]; b[p * 2 + 1][1] = r[3];
            }
            {
                uint32_t addr = bbuf + (wn + 32 + (lane & 7)) * 80
                              + (kb + (((lane >> 3) & 1) << 3)) * 2;
                ldsm2(b[4], addr);
            }
#pragma unroll
            for (int mt = 0; mt < 2; ++mt)
#pragma unroll
                for (int nt = 0; nt < 5; ++nt)
                    mma16816(acc[mt][nt], a[mt], b[nt]);
        }
        __syncthreads();
    }

    // ---- epilogue: frags -> smem C, then gate recombine ----
    float* Cs = reinterpret_cast<float*>(smem);     // [128][84]
#pragma unroll
    for (int mt = 0; mt < 2; ++mt)
#pragma unroll
        for (int nt = 0; nt < 5; ++nt) {
            int m  = wm + mt * 16 + (lane >> 2);
            int nn = wn + nt * 8 + (lane & 3) * 2;
            Cs[m * 84 + nn]           = acc[mt][nt][0];
            Cs[m * 84 + nn + 1]       = acc[mt][nt][1];
            Cs[(m + 8) * 84 + nn]     = acc[mt][nt][2];
            Cs[(m + 8) * 84 + nn + 1] = acc[mt][nt][3];
        }
    __syncthreads();

#pragma unroll
    for (int pass = 0; pass < 8; ++pass) {
        const int task = t + pass * 256;      // 128 nodes x 16 units
        const int m = task >> 4;
        const int u = task & 15;
        if (m0 + m >= n) continue;
        const int gn = gn0 + m;
        const int j  = cb * 16 + u;

        const float* cp = &Cs[m * 84 + u * 5];
        float zi = cp[0] + g_bias[j * 5 + 0];
        float zo = cp[1] + g_bias[j * 5 + 1];
        float zu = cp[2] + g_bias[j * 5 + 2];
        float vi = sigmoidf_(zi);
        float vo = sigmoidf_(zo);
        float vu = tanhf(zu);
        float cv = vi * vu;
        if (HASCH) {
            float zf0 = cp[3] + g_bias[j * 5 + 3];
            float zf1 = cp[4] + g_bias[j * 5 + 4];
            cv += sigmoidf_(zf0) * g_c[(size_t)(2 * gn + 1) * H + j]
                + sigmoidf_(zf1) * g_c[(size_t)(2 * gn + 2) * H + j];
        }
        float h = vo * tanhf(cv);
        __nv_bfloat16 hh = __float2bfloat16(h);
        g_hhi[(size_t)gn * H + j] = hh;
        g_hlo[(size_t)gn * H + j] = __float2bfloat16(h - __bfloat162float(hh));
        g_c  [(size_t)gn * H + j] = cv;
        if (out != nullptr && gn == 0) {
            out[j]     = h;
            out[H + j] = cv;
        }
    }
}

// ---------------- host launcher ----------------
extern "C" void kernel_launch(void* const* d_in, const int* in_sizes, int n_in,
                              void* d_out, int out_size)
{
    const float* emb = (const float*)d_in[0];
    const float* Wi  = (const float*)d_in[1];
    const float* bi  = (const float*)d_in[2];
    const float* Ui  = (const float*)d_in[3];
    const float* Wo  = (const float*)d_in[4];
    const float* bo  = (const float*)d_in[5];
    const float* Uo  = (const float*)d_in[6];
    const float* Wu  = (const float*)d_in[7];
    const float* bu  = (const float*)d_in[8];
    const float* Uu  = (const float*)d_in[9];
    const float* Wf  = (const float*)d_in[10];
    const float* bf  = (const float*)d_in[11];
    const float* Uf  = (const float*)d_in[12];

    split_emb_kernel<<<2048, 256>>>(emb);
    pack_w_kernel<<<1024, 256>>>(Wi, bi, Ui, Wo, bo, Uo, Wu, bu, Uu, Wf, bf, Uf);

    // leaves: level 15, n = 32768, K = 256 (no children)
    {
        int n = 1 << (DEPTH - 1);
        int start = n - 1;
        dim3 grid(16, n / 128);
        hmma_level_kernel<false><<<grid, 256, SMEM_DYN>>>(start, n, nullptr);
    }
    // internal levels bottom-up
    for (int l = DEPTH - 2; l >= 0; --l) {
        int n = 1 << l;
        int start = n - 1;
        dim3 grid(16, (n + 127) / 128);
        float* outp = (l == 0) ? (float*)d_out : nullptr;
        hmma_level_kernel<true><<<grid, 256, SMEM_DYN>>>(start, n, outp);
    }
}

// round 5
// speedup vs baseline: 2.8522x; 1.3849x over previous
#include <cuda_runtime.h>
#include <cuda_bf16.h>
#include <cstdint>
#include <math.h>

#define DEPTH 16
#define NN    65535
#define H     256
#define KIN   768
#define NCOL  1280           // 5 gates * 256 units, col = j*5+g

// ---------------- device scratch (no cudaMalloc allowed) ----------------
__device__ __nv_bfloat16 g_ehi[(size_t)NN * H];
__device__ __nv_bfloat16 g_elo[(size_t)NN * H];
__device__ __nv_bfloat16 g_hhi[(size_t)NN * H];
__device__ __nv_bfloat16 g_hlo[(size_t)NN * H];
__device__ float         g_c  [(size_t)NN * H];
__device__ __nv_bfloat16 g_Bhi[(size_t)NCOL * KIN];   // [col][k]
__device__ __nv_bfloat16 g_Blo[(size_t)NCOL * KIN];
__device__ float         g_bias[NCOL];

// ---------------- smem layouts ----------------
// Main kernel: A stage 128 x 144B, B stage 80 x 144B, 2 stages.
static constexpr int ASTG = 128 * 144;     // 18432
static constexpr int BSTG = 80 * 144;      // 11520
static constexpr int OFF_BS_MAIN = 2 * ASTG;               // 36864
static constexpr int SMEM_MAIN   = 2 * ASTG + 2 * BSTG;    // 59904
// Small kernel: per (slice, stage): A 32x144 + B 80x144 = 16128, 4 slices x 2 stages.
static constexpr int SLST = 32 * 144 + 80 * 144;  // 16128
static constexpr int SMEM_SMALL = 8 * SLST;       // 129024

// ---------------- PTX helpers (baseline sm_80+, no 'a' features) ----------------
__device__ __forceinline__ uint32_t smem_to_u32(const void* p) {
    uint32_t a;
    asm("{ .reg .u64 t; cvta.to.shared.u64 t, %1; cvt.u32.u64 %0, t; }" : "=r"(a) : "l"(p));
    return a;
}
__device__ __forceinline__ void cpasync16(uint32_t dst, const void* src) {
    asm volatile("cp.async.cg.shared.global [%0], [%1], 16;" :: "r"(dst), "l"(src) : "memory");
}
#define CP_COMMIT() asm volatile("cp.async.commit_group;" ::: "memory")
#define CP_WAIT(N)  asm volatile("cp.async.wait_group %0;" :: "n"(N) : "memory")

__device__ __forceinline__ void ldsm4(uint32_t* r, uint32_t addr) {
    asm volatile("ldmatrix.sync.aligned.m8n8.x4.shared.b16 {%0,%1,%2,%3}, [%4];"
        : "=r"(r[0]), "=r"(r[1]), "=r"(r[2]), "=r"(r[3]) : "r"(addr));
}
__device__ __forceinline__ void ldsm2(uint32_t* r, uint32_t addr) {
    asm volatile("ldmatrix.sync.aligned.m8n8.x2.shared.b16 {%0,%1}, [%2];"
        : "=r"(r[0]), "=r"(r[1]) : "r"(addr));
}
__device__ __forceinline__ void mma16816(float* d, const uint32_t* a, const uint32_t* b) {
    asm volatile("mma.sync.aligned.m16n8k16.row.col.f32.bf16.bf16.f32 "
        "{%0,%1,%2,%3}, {%4,%5,%6,%7}, {%8,%9}, {%0,%1,%2,%3};"
        : "+f"(d[0]), "+f"(d[1]), "+f"(d[2]), "+f"(d[3])
        : "r"(a[0]), "r"(a[1]), "r"(a[2]), "r"(a[3]), "r"(b[0]), "r"(b[1]));
}

__device__ __forceinline__ float sigmoidf_(float x) { return 1.f / (1.f + expf(-x)); }

// One KT=64 chunk of warp-tile MMA: A rows [wm, wm+32), B rows [wn, wn+40).
__device__ __forceinline__ void chunk_mma(uint32_t abuf, uint32_t bbuf,
                                          int wm, int wn, int lane,
                                          float acc[2][5][4]) {
#pragma unroll
    for (int k16 = 0; k16 < 4; ++k16) {
        const int kb = k16 * 16;
        uint32_t a[2][4], b[5][2];
#pragma unroll
        for (int mt = 0; mt < 2; ++mt) {
            uint32_t addr = abuf + (wm + mt * 16 + (lane & 15)) * 144
                          + (kb + ((lane >> 4) << 3)) * 2;
            ldsm4(a[mt], addr);
        }
#pragma unroll
        for (int p = 0; p < 2; ++p) {
            uint32_t r[4];
            uint32_t addr = bbuf
                + (wn + p * 16 + ((lane >> 4) << 3) + (lane & 7)) * 144
                + (kb + (((lane >> 3) & 1) << 3)) * 2;
            ldsm4(r, addr);
            b[p * 2 + 0][0] = r[0]; b[p * 2 + 0][1] = r[1];
            b[p * 2 + 1][0] = r[2]; b[p * 2 + 1][1] = r[3];
        }
        {
            uint32_t addr = bbuf + (wn + 32 + (lane & 7)) * 144
                          + (kb + (((lane >> 3) & 1) << 3)) * 2;
            ldsm2(b[4], addr);
        }
#pragma unroll
        for (int mt = 0; mt < 2; ++mt)
#pragma unroll
            for (int nt = 0; nt < 5; ++nt)
                mma16816(acc[mt][nt], a[mt], b[nt]);
    }
}

// ---------------- pack kernels ----------------
__global__ void split_emb_kernel(const float* __restrict__ emb) {
    int idx = blockIdx.x * blockDim.x + threadIdx.x;
    int stride = gridDim.x * blockDim.x;
    const int total4 = (NN * H) / 4;
    for (int i = idx; i < total4; i += stride) {
        float4 v = reinterpret_cast<const float4*>(emb)[i];
        __nv_bfloat16 hh[4], hl[4];
        float f[4] = {v.x, v.y, v.z, v.w};
#pragma unroll
        for (int k = 0; k < 4; ++k) {
            hh[k] = __float2bfloat16(f[k]);
            hl[k] = __float2bfloat16(f[k] - __bfloat162float(hh[k]));
        }
        reinterpret_cast<uint2*>(g_ehi)[i] = *reinterpret_cast<uint2*>(hh);
        reinterpret_cast<uint2*>(g_elo)[i] = *reinterpret_cast<uint2*>(hl);
    }
}

__global__ void pack_w_kernel(
    const float* __restrict__ Wi, const float* __restrict__ bi, const float* __restrict__ Ui,
    const float* __restrict__ Wo, const float* __restrict__ bo, const float* __restrict__ Uo,
    const float* __restrict__ Wu, const float* __restrict__ bu, const float* __restrict__ Uu,
    const float* __restrict__ Wf, const float* __restrict__ bf, const float* __restrict__ Uf)
{
    int idx = blockIdx.x * blockDim.x + threadIdx.x;
    int stride = gridDim.x * blockDim.x;
    if (idx < NCOL) {
        int j = idx / 5, g = idx % 5;
        g_bias[idx] = (g == 0) ? bi[j] : (g == 1) ? bo[j] : (g == 2) ? bu[j] : bf[j];
    }
    for (int e = idx; e < NCOL * KIN; e += stride) {
        int col = e / KIN;
        int k   = e - col * KIN;
        int j = col / 5, g = col % 5;
        float v = 0.f;
        if (k < H) {
            const float* W = (g == 0) ? Wi : (g == 1) ? Wo : (g == 2) ? Wu : Wf;
            v = W[j * H + k];
        } else if (k < 2 * H) {
            int kk = k - H;
            if      (g == 0) v = Ui[j * H + kk];
            else if (g == 1) v = Uo[j * H + kk];
            else if (g == 2) v = Uu[j * H + kk];
            else if (g == 3) v = Uf[j * H + kk];
        } else {
            int kk = k - 2 * H;
            if      (g == 0) v = Ui[H * H + j * H + kk];
            else if (g == 1) v = Uo[H * H + j * H + kk];
            else if (g == 2) v = Uu[H * H + j * H + kk];
            else if (g == 4) v = Uf[H * H + j * H + kk];
        }
        __nv_bfloat16 hi = __float2bfloat16(v);
        g_Bhi[e] = hi;
        g_Blo[e] = __float2bfloat16(v - __bfloat162float(hi));
    }
}

// ---------------- main level kernel: 128 nodes x 80 cols, KT=64 pipelined ----------------
template <bool HASCH>
__global__ void __launch_bounds__(256, 2) hmma_level_kernel(
    int start, int n, float* __restrict__ out)
{
    extern __shared__ char smem[];
    const uint32_t sbase = smem_to_u32(smem);

    const int t    = threadIdx.x;
    const int lane = t & 31;
    const int wid  = t >> 5;
    const int cb   = blockIdx.x;          // 0..15 column blocks (80 cols each)
    const int m0   = blockIdx.y * 128;
    const int gn0  = start + m0;
    const int col0 = cb * 80;

    constexpr int KL  = HASCH ? KIN : H;  // 768 / 256
    constexpr int NCH = 3 * KL / 64;      // 36 / 12

    float acc[2][5][4];
#pragma unroll
    for (int mt = 0; mt < 2; ++mt)
#pragma unroll
        for (int nt = 0; nt < 5; ++nt)
#pragma unroll
            for (int r = 0; r < 4; ++r) acc[mt][nt][r] = 0.f;

    auto load_chunk = [&](int c, int st) {
        const int kk = c * 64;
        const int s  = kk / KL;
        const int k  = kk - s * KL;
        const __nv_bfloat16* abase;
        int astride;
        if (!HASCH || k < H) {
            abase = (s == 1 ? g_elo : g_ehi) + (size_t)gn0 * H + k;
            astride = H;
        } else if (k < 2 * H) {
            abase = (s == 1 ? g_hlo : g_hhi) + (size_t)(2 * gn0 + 1) * H + (k - H);
            astride = 2 * H;
        } else {
            abase = (s == 1 ? g_hlo : g_hhi) + (size_t)(2 * gn0 + 2) * H + (k - 2 * H);
            astride = 2 * H;
        }
        const __nv_bfloat16* bbase = (s == 2 ? g_Blo : g_Bhi) + (size_t)col0 * KIN + k;
        const uint32_t adst = sbase + st * ASTG;
        const uint32_t bdst = sbase + OFF_BS_MAIN + st * BSTG;
#pragma unroll
        for (int i = 0; i < 7; ++i) {
            int idx = t + i * 256;
            if (idx < 1024) {                       // A: 128 rows x 8 segs
                int row = idx >> 3, seg = idx & 7;
                cpasync16(adst + row * 144 + seg * 16,
                          abase + (size_t)row * astride + seg * 8);
            } else if (idx < 1664) {                // B: 80 rows x 8 segs
                int r2 = idx - 1024;
                int row = r2 >> 3, seg = r2 & 7;
                cpasync16(bdst + row * 144 + seg * 16,
                          bbase + (size_t)row * KIN + seg * 8);
            }
        }
        CP_COMMIT();
    };

    load_chunk(0, 0);

    const int wm = (wid & 3) * 32;
    const int wn = (wid >> 2) * 40;

    for (int c = 0; c < NCH; ++c) {
        const int st = c & 1;
        if (c + 1 < NCH) { load_chunk(c + 1, st ^ 1); CP_WAIT(1); }
        else             { CP_WAIT(0); }
        __syncthreads();
        chunk_mma(sbase + st * ASTG, sbase + OFF_BS_MAIN + st * BSTG,
                  wm, wn, lane, acc);
        __syncthreads();
    }

    // ---- epilogue: frags -> smem C, then gate recombine ----
    float* Cs = reinterpret_cast<float*>(smem);     // [128][84]
#pragma unroll
    for (int mt = 0; mt < 2; ++mt)
#pragma unroll
        for (int nt = 0; nt < 5; ++nt) {
            int m  = wm + mt * 16 + (lane >> 2);
            int nn = wn + nt * 8 + (lane & 3) * 2;
            Cs[m * 84 + nn]           = acc[mt][nt][0];
            Cs[m * 84 + nn + 1]       = acc[mt][nt][1];
            Cs[(m + 8) * 84 + nn]     = acc[mt][nt][2];
            Cs[(m + 8) * 84 + nn + 1] = acc[mt][nt][3];
        }
    __syncthreads();

#pragma unroll
    for (int pass = 0; pass < 8; ++pass) {
        const int task = t + pass * 256;      // 128 nodes x 16 units
        const int m = task >> 4;
        const int u = task & 15;
        if (m0 + m >= n) continue;
        const int gn = gn0 + m;
        const int j  = cb * 16 + u;

        const float* cp = &Cs[m * 84 + u * 5];
        float zi = cp[0] + g_bias[j * 5 + 0];
        float zo = cp[1] + g_bias[j * 5 + 1];
        float zu = cp[2] + g_bias[j * 5 + 2];
        float vi = sigmoidf_(zi);
        float vo = sigmoidf_(zo);
        float vu = tanhf(zu);
        float cv = vi * vu;
        if (HASCH) {
            float zf0 = cp[3] + g_bias[j * 5 + 3];
            float zf1 = cp[4] + g_bias[j * 5 + 4];
            cv += sigmoidf_(zf0) * g_c[(size_t)(2 * gn + 1) * H + j]
                + sigmoidf_(zf1) * g_c[(size_t)(2 * gn + 2) * H + j];
        }
        float h = vo * tanhf(cv);
        __nv_bfloat16 hh = __float2bfloat16(h);
        g_hhi[(size_t)gn * H + j] = hh;
        g_hlo[(size_t)gn * H + j] = __float2bfloat16(h - __bfloat162float(hh));
        g_c  [(size_t)gn * H + j] = cv;
        if (out != nullptr && gn == 0) {
            out[j]     = h;
            out[H + j] = cv;
        }
    }
}

// ---------------- small-level kernel: split-K across warps, M tile = 32 ----------------
// 8 warps = 4 K-slices x 2 N-halves. Each warp: 9 of 36 KT=64 chunks.
// Internal levels only (always has children), n <= 512.
__global__ void __launch_bounds__(256) smallk_kernel(int start, int n, float* __restrict__ out)
{
    extern __shared__ char smem[];
    const uint32_t sbase = smem_to_u32(smem);

    const int t    = threadIdx.x;
    const int lane = t & 31;
    const int wid  = t >> 5;
    const int cb   = blockIdx.x;
    const int m0   = blockIdx.y * 32;
    const int gn0  = start + m0;
    const int col0 = cb * 80;

    const int ks = wid >> 1;              // K-slice 0..3
    const int wn = (wid & 1) * 40;        // N half

    constexpr int PER = 9;                // chunks per slice (36/4)

    float acc[2][5][4];
#pragma unroll
    for (int mt = 0; mt < 2; ++mt)
#pragma unroll
        for (int nt = 0; nt < 5; ++nt)
#pragma unroll
            for (int r = 0; r < 4; ++r) acc[mt][nt][r] = 0.f;

    auto load_step = [&](int step, int st) {
#pragma unroll
        for (int i = 0; i < 14; ++i) {            // 4 slices x (256 A + 640 B) = 3584 ops
            int idx = t + i * 256;
            int sl  = idx / 896;
            int rem = idx - sl * 896;
            int c   = sl * PER + step;
            int kp  = c * 64;
            int s   = kp / KIN;
            int k   = kp - s * KIN;
            uint32_t sbuf = sbase + (sl * 2 + st) * SLST;
            if (rem < 256) {                      // A: 32 rows x 8 segs
                int row = rem >> 3, seg = rem & 7;
                const __nv_bfloat16* abase;
                int astride;
                if (k < H) {
                    abase = (s == 1 ? g_elo : g_ehi) + (size_t)gn0 * H + k;
                    astride = H;
                } else if (k < 2 * H) {
                    abase = (s == 1 ? g_hlo : g_hhi) + (size_t)(2 * gn0 + 1) * H + (k - H);
                    astride = 2 * H;
                } else {
                    abase = (s == 1 ? g_hlo : g_hhi) + (size_t)(2 * gn0 + 2) * H + (k - 2 * H);
                    astride = 2 * H;
                }
                cpasync16(sbuf + row * 144 + seg * 16,
                          abase + (size_t)row * astride + seg * 8);
            } else {                              // B: 80 rows x 8 segs
                int r2 = rem - 256;
                int row = r2 >> 3, seg = r2 & 7;
                const __nv_bfloat16* bbase = (s == 2 ? g_Blo : g_Bhi) + (size_t)col0 * KIN + k;
                cpasync16(sbuf + 32 * 144 + row * 144 + seg * 16,
                          bbase + (size_t)row * KIN + seg * 8);
            }
        }
        CP_COMMIT();
    };

    load_step(0, 0);

    for (int step = 0; step < PER; ++step) {
        const int st = step & 1;
        if (step + 1 < PER) { load_step(step + 1, st ^ 1); CP_WAIT(1); }
        else                { CP_WAIT(0); }
        __syncthreads();
        const uint32_t abuf = sbase + (ks * 2 + st) * SLST;
        chunk_mma(abuf, abuf + 32 * 144, 0, wn, lane, acc);
        __syncthreads();
    }

    // ---- reduce 4 K-slices through smem, then gates ----
    float* Cp = reinterpret_cast<float*>(smem);   // [4][32][84] = 43008 B (aliases stages)
#pragma unroll
    for (int mt = 0; mt < 2; ++mt)
#pragma unroll
        for (int nt = 0; nt < 5; ++nt) {
            int m  = mt * 16 + (lane >> 2);
            int nn = wn + nt * 8 + (lane & 3) * 2;
            float* dst = Cp + ks * (32 * 84);
            dst[m * 84 + nn]           = acc[mt][nt][0];
            dst[m * 84 + nn + 1]       = acc[mt][nt][1];
            dst[(m + 8) * 84 + nn]     = acc[mt][nt][2];
            dst[(m + 8) * 84 + nn + 1] = acc[mt][nt][3];
        }
    __syncthreads();

#pragma unroll
    for (int pass = 0; pass < 2; ++pass) {
        const int task = t + pass * 256;          // 32 nodes x 16 units
        const int m = task >> 4;
        const int u = task & 15;
        if (m0 + m >= n) continue;
        const int gn = gn0 + m;
        const int j  = cb * 16 + u;

        float z[5];
#pragma unroll
        for (int g = 0; g < 5; ++g) {
            float s = g_bias[j * 5 + g];
#pragma unroll
            for (int sl = 0; sl < 4; ++sl)
                s += Cp[sl * (32 * 84) + m * 84 + u * 5 + g];
            z[g] = s;
        }
        float vi = sigmoidf_(z[0]);
        float vo = sigmoidf_(z[1]);
        float vu = tanhf(z[2]);
        float cv = vi * vu
                 + sigmoidf_(z[3]) * g_c[(size_t)(2 * gn + 1) * H + j]
                 + sigmoidf_(z[4]) * g_c[(size_t)(2 * gn + 2) * H + j];
        float h = vo * tanhf(cv);
        __nv_bfloat16 hh = __float2bfloat16(h);
        g_hhi[(size_t)gn * H + j] = hh;
        g_hlo[(size_t)gn * H + j] = __float2bfloat16(h - __bfloat162float(hh));
        g_c  [(size_t)gn * H + j] = cv;
        if (out != nullptr && gn == 0) {
            out[j]     = h;
            out[H + j] = cv;
        }
    }
}

// ---------------- host launcher ----------------
extern "C" void kernel_launch(void* const* d_in, const int* in_sizes, int n_in,
                              void* d_out, int out_size)
{
    const float* emb = (const float*)d_in[0];
    const float* Wi  = (const float*)d_in[1];
    const float* bi  = (const float*)d_in[2];
    const float* Ui  = (const float*)d_in[3];
    const float* Wo  = (const float*)d_in[4];
    const float* bo  = (const float*)d_in[5];
    const float* Uo  = (const float*)d_in[6];
    const float* Wu  = (const float*)d_in[7];
    const float* bu  = (const float*)d_in[8];
    const float* Uu  = (const float*)d_in[9];
    const float* Wf  = (const float*)d_in[10];
    const float* bf  = (const float*)d_in[11];
    const float* Uf  = (const float*)d_in[12];

    cudaFuncSetAttribute(hmma_level_kernel<false>, cudaFuncAttributeMaxDynamicSharedMemorySize, SMEM_MAIN);
    cudaFuncSetAttribute(hmma_level_kernel<true>,  cudaFuncAttributeMaxDynamicSharedMemorySize, SMEM_MAIN);
    cudaFuncSetAttribute(smallk_kernel,            cudaFuncAttributeMaxDynamicSharedMemorySize, SMEM_SMALL);

    split_emb_kernel<<<2048, 256>>>(emb);
    pack_w_kernel<<<1024, 256>>>(Wi, bi, Ui, Wo, bo, Uo, Wu, bu, Uu, Wf, bf, Uf);

    // leaves: level 15, n = 32768, K' = 768 (no children)
    {
        int n = 1 << (DEPTH - 1);
        int start = n - 1;
        dim3 grid(16, n / 128);
        hmma_level_kernel<false><<<grid, 256, SMEM_MAIN>>>(start, n, nullptr);
    }
    // internal levels bottom-up
    for (int l = DEPTH - 2; l >= 0; --l) {
        int n = 1 << l;
        int start = n - 1;
        float* outp = (l == 0) ? (float*)d_out : nullptr;
        if (n >= 1024) {
            dim3 grid(16, n / 128);
            hmma_level_kernel<true><<<grid, 256, SMEM_MAIN>>>(start, n, outp);
        } else {
            dim3 grid(16, (n + 31) / 32);
            smallk_kernel<<<grid, 256, SMEM_SMALL>>>(start, n, outp);
        }
    }
}

// round 6
// speedup vs baseline: 3.9355x; 1.3798x over previous
#include <cuda_runtime.h>
#include <cuda_fp16.h>
#include <cstdint>
#include <math.h>

#define DEPTH 16
#define NN    65535
#define H     256
#define KIN   768
#define NCOL  1280           // 5 gates * 256 units, col = j*5+g

// ---------------- device scratch (no cudaMalloc allowed) ----------------
__device__ __half g_ehi[(size_t)NN * H];
__device__ __half g_elo[(size_t)NN * H];
__device__ __half g_hhi[(size_t)NN * H];
__device__ __half g_hlo[(size_t)NN * H];
__device__ float  g_c  [(size_t)NN * H];
__device__ __half g_B  [(size_t)NCOL * KIN];   // [col][k], fp16 hi only
__device__ float  g_bias[NCOL];

// ---------------- smem layouts ----------------
static constexpr int ASTG = 128 * 144;     // 18432
static constexpr int BSTG = 80 * 144;      // 11520
static constexpr int OFF_BS_MAIN = 2 * ASTG;               // 36864
static constexpr int SMEM_MAIN   = 2 * ASTG + 2 * BSTG;    // 59904
static constexpr int SLST = 32 * 144 + 80 * 144;  // 16128
static constexpr int SMEM_SMALL = 8 * SLST;       // 129024

// ---------------- PTX helpers (baseline sm_80+) ----------------
__device__ __forceinline__ uint32_t smem_to_u32(const void* p) {
    uint32_t a;
    asm("{ .reg .u64 t; cvta.to.shared.u64 t, %1; cvt.u32.u64 %0, t; }" : "=r"(a) : "l"(p));
    return a;
}
__device__ __forceinline__ void cpasync16(uint32_t dst, const void* src) {
    asm volatile("cp.async.cg.shared.global [%0], [%1], 16;" :: "r"(dst), "l"(src) : "memory");
}
#define CP_COMMIT() asm volatile("cp.async.commit_group;" ::: "memory")
#define CP_WAIT(N)  asm volatile("cp.async.wait_group %0;" :: "n"(N) : "memory")

__device__ __forceinline__ void ldsm4(uint32_t* r, uint32_t addr) {
    asm volatile("ldmatrix.sync.aligned.m8n8.x4.shared.b16 {%0,%1,%2,%3}, [%4];"
        : "=r"(r[0]), "=r"(r[1]), "=r"(r[2]), "=r"(r[3]) : "r"(addr));
}
__device__ __forceinline__ void ldsm2(uint32_t* r, uint32_t addr) {
    asm volatile("ldmatrix.sync.aligned.m8n8.x2.shared.b16 {%0,%1}, [%2];"
        : "=r"(r[0]), "=r"(r[1]) : "r"(addr));
}
__device__ __forceinline__ void mma16816(float* d, const uint32_t* a, const uint32_t* b) {
    asm volatile("mma.sync.aligned.m16n8k16.row.col.f32.f16.f16.f32 "
        "{%0,%1,%2,%3}, {%4,%5,%6,%7}, {%8,%9}, {%0,%1,%2,%3};"
        : "+f"(d[0]), "+f"(d[1]), "+f"(d[2]), "+f"(d[3])
        : "r"(a[0]), "r"(a[1]), "r"(a[2]), "r"(a[3]), "r"(b[0]), "r"(b[1]));
}

__device__ __forceinline__ float sigmoidf_(float x) { return 1.f / (1.f + expf(-x)); }

// One KT=64 chunk of warp-tile MMA: A rows [wm, wm+32), B rows [wn, wn+40).
__device__ __forceinline__ void chunk_mma(uint32_t abuf, uint32_t bbuf,
                                          int wm, int wn, int lane,
                                          float acc[2][5][4]) {
#pragma unroll
    for (int k16 = 0; k16 < 4; ++k16) {
        const int kb = k16 * 16;
        uint32_t a[2][4], b[5][2];
#pragma unroll
        for (int mt = 0; mt < 2; ++mt) {
            uint32_t addr = abuf + (wm + mt * 16 + (lane & 15)) * 144
                          + (kb + ((lane >> 4) << 3)) * 2;
            ldsm4(a[mt], addr);
        }
#pragma unroll
        for (int p = 0; p < 2; ++p) {
            uint32_t r[4];
            uint32_t addr = bbuf
                + (wn + p * 16 + ((lane >> 4) << 3) + (lane & 7)) * 144
                + (kb + (((lane >> 3) & 1) << 3)) * 2;
            ldsm4(r, addr);
            b[p * 2 + 0][0] = r[0]; b[p * 2 + 0][1] = r[1];
            b[p * 2 + 1][0] = r[2]; b[p * 2 + 1][1] = r[3];
        }
        {
            uint32_t addr = bbuf + (wn + 32 + (lane & 7)) * 144
                          + (kb + (((lane >> 3) & 1) << 3)) * 2;
            ldsm2(b[4], addr);
        }
#pragma unroll
        for (int mt = 0; mt < 2; ++mt)
#pragma unroll
            for (int nt = 0; nt < 5; ++nt)
                mma16816(acc[mt][nt], a[mt], b[nt]);
    }
}

// ---------------- pack kernels ----------------
__global__ void split_emb_kernel(const float* __restrict__ emb) {
    int idx = blockIdx.x * blockDim.x + threadIdx.x;
    int stride = gridDim.x * blockDim.x;
    const int total4 = (NN * H) / 4;
    for (int i = idx; i < total4; i += stride) {
        float4 v = reinterpret_cast<const float4*>(emb)[i];
        __half hh[4], hl[4];
        float f[4] = {v.x, v.y, v.z, v.w};
#pragma unroll
        for (int k = 0; k < 4; ++k) {
            hh[k] = __float2half(f[k]);
            hl[k] = __float2half(f[k] - __half2float(hh[k]));
        }
        reinterpret_cast<uint2*>(g_ehi)[i] = *reinterpret_cast<uint2*>(hh);
        reinterpret_cast<uint2*>(g_elo)[i] = *reinterpret_cast<uint2*>(hl);
    }
}

__global__ void pack_w_kernel(
    const float* __restrict__ Wi, const float* __restrict__ bi, const float* __restrict__ Ui,
    const float* __restrict__ Wo, const float* __restrict__ bo, const float* __restrict__ Uo,
    const float* __restrict__ Wu, const float* __restrict__ bu, const float* __restrict__ Uu,
    const float* __restrict__ Wf, const float* __restrict__ bf, const float* __restrict__ Uf)
{
    int idx = blockIdx.x * blockDim.x + threadIdx.x;
    int stride = gridDim.x * blockDim.x;
    if (idx < NCOL) {
        int j = idx / 5, g = idx % 5;
        g_bias[idx] = (g == 0) ? bi[j] : (g == 1) ? bo[j] : (g == 2) ? bu[j] : bf[j];
    }
    for (int e = idx; e < NCOL * KIN; e += stride) {
        int col = e / KIN;
        int k   = e - col * KIN;
        int j = col / 5, g = col % 5;
        float v = 0.f;
        if (k < H) {
            const float* W = (g == 0) ? Wi : (g == 1) ? Wo : (g == 2) ? Wu : Wf;
            v = W[j * H + k];
        } else if (k < 2 * H) {
            int kk = k - H;
            if      (g == 0) v = Ui[j * H + kk];
            else if (g == 1) v = Uo[j * H + kk];
            else if (g == 2) v = Uu[j * H + kk];
            else if (g == 3) v = Uf[j * H + kk];
        } else {
            int kk = k - 2 * H;
            if      (g == 0) v = Ui[H * H + j * H + kk];
            else if (g == 1) v = Uo[H * H + j * H + kk];
            else if (g == 2) v = Uu[H * H + j * H + kk];
            else if (g == 4) v = Uf[H * H + j * H + kk];
        }
        g_B[e] = __float2half(v);
    }
}

// ---------------- main level kernel: 128 nodes x 80 cols, KT=64, 1 sync/chunk ----------------
// Extended K' = 2*KL: split 0 = A_hi * B, split 1 = A_lo * B.
template <bool HASCH>
__global__ void __launch_bounds__(256, 2) hmma_level_kernel(
    int start, int n, float* __restrict__ out)
{
    extern __shared__ char smem[];
    const uint32_t sbase = smem_to_u32(smem);

    const int t    = threadIdx.x;
    const int lane = t & 31;
    const int wid  = t >> 5;
    const int cb   = blockIdx.x;          // 0..15 column blocks (80 cols each)
    const int m0   = blockIdx.y * 128;
    const int gn0  = start + m0;
    const int col0 = cb * 80;

    constexpr int KL  = HASCH ? KIN : H;  // 768 / 256
    constexpr int NCH = 2 * KL / 64;      // 24 / 8

    float acc[2][5][4];
#pragma unroll
    for (int mt = 0; mt < 2; ++mt)
#pragma unroll
        for (int nt = 0; nt < 5; ++nt)
#pragma unroll
            for (int r = 0; r < 4; ++r) acc[mt][nt][r] = 0.f;

    auto load_chunk = [&](int c, int st) {
        const int kk = c * 64;
        const int s  = kk / KL;
        const int k  = kk - s * KL;
        const __half* abase;
        int astride;
        if (!HASCH || k < H) {
            abase = (s == 1 ? g_elo : g_ehi) + (size_t)gn0 * H + k;
            astride = H;
        } else if (k < 2 * H) {
            abase = (s == 1 ? g_hlo : g_hhi) + (size_t)(2 * gn0 + 1) * H + (k - H);
            astride = 2 * H;
        } else {
            abase = (s == 1 ? g_hlo : g_hhi) + (size_t)(2 * gn0 + 2) * H + (k - 2 * H);
            astride = 2 * H;
        }
        const __half* bbase = g_B + (size_t)col0 * KIN + k;
        const uint32_t adst = sbase + st * ASTG;
        const uint32_t bdst = sbase + OFF_BS_MAIN + st * BSTG;
#pragma unroll
        for (int i = 0; i < 7; ++i) {
            int idx = t + i * 256;
            if (idx < 1024) {                       // A: 128 rows x 8 segs
                int row = idx >> 3, seg = idx & 7;
                cpasync16(adst + row * 144 + seg * 16,
                          abase + (size_t)row * astride + seg * 8);
            } else if (idx < 1664) {                // B: 80 rows x 8 segs
                int r2 = idx - 1024;
                int row = r2 >> 3, seg = r2 & 7;
                cpasync16(bdst + row * 144 + seg * 16,
                          bbase + (size_t)row * KIN + seg * 8);
            }
        }
        CP_COMMIT();
    };

    load_chunk(0, 0);

    const int wm = (wid & 3) * 32;
    const int wn = (wid >> 2) * 40;

    for (int c = 0; c < NCH; ++c) {
        const int st = c & 1;
        CP_WAIT(0);              // this warp's share of load(c) done
        __syncthreads();         // all shares visible; all warps past mma(c-1)
        if (c + 1 < NCH) load_chunk(c + 1, st ^ 1);
        chunk_mma(sbase + st * ASTG, sbase + OFF_BS_MAIN + st * BSTG,
                  wm, wn, lane, acc);
    }
    __syncthreads();             // protect stage smem before aliasing as Cs

    // ---- epilogue: frags -> smem C, then gate recombine ----
    float* Cs = reinterpret_cast<float*>(smem);     // [128][84]
#pragma unroll
    for (int mt = 0; mt < 2; ++mt)
#pragma unroll
        for (int nt = 0; nt < 5; ++nt) {
            int m  = wm + mt * 16 + (lane >> 2);
            int nn = wn + nt * 8 + (lane & 3) * 2;
            Cs[m * 84 + nn]           = acc[mt][nt][0];
            Cs[m * 84 + nn + 1]       = acc[mt][nt][1];
            Cs[(m + 8) * 84 + nn]     = acc[mt][nt][2];
            Cs[(m + 8) * 84 + nn + 1] = acc[mt][nt][3];
        }
    __syncthreads();

#pragma unroll
    for (int pass = 0; pass < 8; ++pass) {
        const int task = t + pass * 256;      // 128 nodes x 16 units
        const int m = task >> 4;
        const int u = task & 15;
        if (m0 + m >= n) continue;
        const int gn = gn0 + m;
        const int j  = cb * 16 + u;

        const float* cp = &Cs[m * 84 + u * 5];
        float zi = cp[0] + g_bias[j * 5 + 0];
        float zo = cp[1] + g_bias[j * 5 + 1];
        float zu = cp[2] + g_bias[j * 5 + 2];
        float vi = sigmoidf_(zi);
        float vo = sigmoidf_(zo);
        float vu = tanhf(zu);
        float cv = vi * vu;
        if (HASCH) {
            float zf0 = cp[3] + g_bias[j * 5 + 3];
            float zf1 = cp[4] + g_bias[j * 5 + 4];
            cv += sigmoidf_(zf0) * g_c[(size_t)(2 * gn + 1) * H + j]
                + sigmoidf_(zf1) * g_c[(size_t)(2 * gn + 2) * H + j];
        }
        float h = vo * tanhf(cv);
        __half hh = __float2half(h);
        g_hhi[(size_t)gn * H + j] = hh;
        g_hlo[(size_t)gn * H + j] = __float2half(h - __half2float(hh));
        g_c  [(size_t)gn * H + j] = cv;
        if (out != nullptr && gn == 0) {
            out[j]     = h;
            out[H + j] = cv;
        }
    }
}

// ---------------- small-level kernel: split-K across warps, M tile = 32 ----------------
// 8 warps = 4 K-slices x 2 N-halves. Each warp: 6 of 24 KT=64 chunks (K' = 1536).
__global__ void __launch_bounds__(256) smallk_kernel(int start, int n, float* __restrict__ out)
{
    extern __shared__ char smem[];
    const uint32_t sbase = smem_to_u32(smem);

    const int t    = threadIdx.x;
    const int lane = t & 31;
    const int wid  = t >> 5;
    const int cb   = blockIdx.x;
    const int m0   = blockIdx.y * 32;
    const int gn0  = start + m0;
    const int col0 = cb * 80;

    const int ks = wid >> 1;              // K-slice 0..3
    const int wn = (wid & 1) * 40;        // N half

    constexpr int PER = 6;                // chunks per slice (24/4)

    float acc[2][5][4];
#pragma unroll
    for (int mt = 0; mt < 2; ++mt)
#pragma unroll
        for (int nt = 0; nt < 5; ++nt)
#pragma unroll
            for (int r = 0; r < 4; ++r) acc[mt][nt][r] = 0.f;

    auto load_step = [&](int step, int st) {
#pragma unroll
        for (int i = 0; i < 14; ++i) {            // 4 slices x (256 A + 640 B) = 3584 ops
            int idx = t + i * 256;
            int sl  = idx / 896;
            int rem = idx - sl * 896;
            int c   = sl * PER + step;
            int kp  = c * 64;
            int s   = kp / KIN;
            int k   = kp - s * KIN;
            uint32_t sbuf = sbase + (sl * 2 + st) * SLST;
            if (rem < 256) {                      // A: 32 rows x 8 segs
                int row = rem >> 3, seg = rem & 7;
                const __half* abase;
                int astride;
                if (k < H) {
                    abase = (s == 1 ? g_elo : g_ehi) + (size_t)gn0 * H + k;
                    astride = H;
                } else if (k < 2 * H) {
                    abase = (s == 1 ? g_hlo : g_hhi) + (size_t)(2 * gn0 + 1) * H + (k - H);
                    astride = 2 * H;
                } else {
                    abase = (s == 1 ? g_hlo : g_hhi) + (size_t)(2 * gn0 + 2) * H + (k - 2 * H);
                    astride = 2 * H;
                }
                cpasync16(sbuf + row * 144 + seg * 16,
                          abase + (size_t)row * astride + seg * 8);
            } else {                              // B: 80 rows x 8 segs
                int r2 = rem - 256;
                int row = r2 >> 3, seg = r2 & 7;
                const __half* bbase = g_B + (size_t)col0 * KIN + k;
                cpasync16(sbuf + 32 * 144 + row * 144 + seg * 16,
                          bbase + (size_t)row * KIN + seg * 8);
            }
        }
        CP_COMMIT();
    };

    load_step(0, 0);

    for (int step = 0; step < PER; ++step) {
        const int st = step & 1;
        CP_WAIT(0);
        __syncthreads();
        if (step + 1 < PER) load_step(step + 1, st ^ 1);
        const uint32_t abuf = sbase + (ks * 2 + st) * SLST;
        chunk_mma(abuf, abuf + 32 * 144, 0, wn, lane, acc);
    }
    __syncthreads();

    // ---- reduce 4 K-slices through smem, then gates ----
    float* Cp = reinterpret_cast<float*>(smem);   // [4][32][84] = 43008 B (aliases stages)
#pragma unroll
    for (int mt = 0; mt < 2; ++mt)
#pragma unroll
        for (int nt = 0; nt < 5; ++nt) {
            int m  = mt * 16 + (lane >> 2);
            int nn = wn + nt * 8 + (lane & 3) * 2;
            float* dst = Cp + ks * (32 * 84);
            dst[m * 84 + nn]           = acc[mt][nt][0];
            dst[m * 84 + nn + 1]       = acc[mt][nt][1];
            dst[(m + 8) * 84 + nn]     = acc[mt][nt][2];
            dst[(m + 8) * 84 + nn + 1] = acc[mt][nt][3];
        }
    __syncthreads();

#pragma unroll
    for (int pass = 0; pass < 2; ++pass) {
        const int task = t + pass * 256;          // 32 nodes x 16 units
        const int m = task >> 4;
        const int u = task & 15;
        if (m0 + m >= n) continue;
        const int gn = gn0 + m;
        const int j  = cb * 16 + u;

        float z[5];
#pragma unroll
        for (int g = 0; g < 5; ++g) {
            float s = g_bias[j * 5 + g];
#pragma unroll
            for (int sl = 0; sl < 4; ++sl)
                s += Cp[sl * (32 * 84) + m * 84 + u * 5 + g];
            z[g] = s;
        }
        float vi = sigmoidf_(z[0]);
        float vo = sigmoidf_(z[1]);
        float vu = tanhf(z[2]);
        float cv = vi * vu
                 + sigmoidf_(z[3]) * g_c[(size_t)(2 * gn + 1) * H + j]
                 + sigmoidf_(z[4]) * g_c[(size_t)(2 * gn + 2) * H + j];
        float h = vo * tanhf(cv);
        __half hh = __float2half(h);
        g_hhi[(size_t)gn * H + j] = hh;
        g_hlo[(size_t)gn * H + j] = __float2half(h - __half2float(hh));
        g_c  [(size_t)gn * H + j] = cv;
        if (out != nullptr && gn == 0) {
            out[j]     = h;
            out[H + j] = cv;
        }
    }
}

// ---------------- host launcher ----------------
extern "C" void kernel_launch(void* const* d_in, const int* in_sizes, int n_in,
                              void* d_out, int out_size)
{
    const float* emb = (const float*)d_in[0];
    const float* Wi  = (const float*)d_in[1];
    const float* bi  = (const float*)d_in[2];
    const float* Ui  = (const float*)d_in[3];
    const float* Wo  = (const float*)d_in[4];
    const float* bo  = (const float*)d_in[5];
    const float* Uo  = (const float*)d_in[6];
    const float* Wu  = (const float*)d_in[7];
    const float* bu  = (const float*)d_in[8];
    const float* Uu  = (const float*)d_in[9];
    const float* Wf  = (const float*)d_in[10];
    const float* bf  = (const float*)d_in[11];
    const float* Uf  = (const float*)d_in[12];

    cudaFuncSetAttribute(hmma_level_kernel<false>, cudaFuncAttributeMaxDynamicSharedMemorySize, SMEM_MAIN);
    cudaFuncSetAttribute(hmma_level_kernel<true>,  cudaFuncAttributeMaxDynamicSharedMemorySize, SMEM_MAIN);
    cudaFuncSetAttribute(smallk_kernel,            cudaFuncAttributeMaxDynamicSharedMemorySize, SMEM_SMALL);

    split_emb_kernel<<<2048, 256>>>(emb);
    pack_w_kernel<<<1024, 256>>>(Wi, bi, Ui, Wo, bo, Uo, Wu, bu, Uu, Wf, bf, Uf);

    // leaves: level 15, n = 32768, K' = 512 (no children)
    {
        int n = 1 << (DEPTH - 1);
        int start = n - 1;
        dim3 grid(16, n / 128);
        hmma_level_kernel<false><<<grid, 256, SMEM_MAIN>>>(start, n, nullptr);
    }
    // internal levels bottom-up
    for (int l = DEPTH - 2; l >= 0; --l) {
        int n = 1 << l;
        int start = n - 1;
        float* outp = (l == 0) ? (float*)d_out : nullptr;
        if (n >= 1024) {
            dim3 grid(16, n / 128);
            hmma_level_kernel<true><<<grid, 256, SMEM_MAIN>>>(start, n, outp);
        } else {
            dim3 grid(16, (n + 31) / 32);
            smallk_kernel<<<grid, 256, SMEM_SMALL>>>(start, n, outp);
        }
    }
}